// round 11
// baseline (speedup 1.0000x reference)
#include <cuda_runtime.h>
#include <cuda_fp16.h>
#include <math.h>

#define Tsz 512
#define FS 64
#define FC 32
#define H 256
#define LN_EPS 1e-5f

typedef unsigned long long ull;

// fp16 weights, k-major, pair-packed {m1[k,j], m2[k,j]} as one half2 per k-row.
// One uint4 = 4 consecutive k-rows. gh[r4*H + j].
__device__ uint4 gh_s0[(FS / 4) * H];   // {Win0_seq, Wg0_seq}
__device__ uint4 gh_c0[(FC / 4) * H];   // {Win0_ctx, Wg0_ctx}
__device__ uint4 gh_h0[(H / 4) * H];    // {Wg0_h,    Wrec0}
__device__ uint4 gh_x1[(H / 4) * H];    // {Win1,     Wg1_x}
__device__ uint4 gh_h1[(H / 4) * H];    // {Wg1_h,    Wrec1}

__device__ __forceinline__ unsigned pack_h2(float a, float b) {
    __half2 h = __floats2half2_rn(a, b);
    return *reinterpret_cast<unsigned*>(&h);
}

__global__ void setup_kernel(const float* __restrict__ Win0,
                             const float* __restrict__ Wrec0,
                             const float* __restrict__ Wg0,
                             const float* __restrict__ Win1,
                             const float* __restrict__ Wrec1,
                             const float* __restrict__ Wg1) {
    int j = threadIdx.x;
    int r = blockIdx.x;
    uint4 u;
    if (r < 16) {                       // s0
        int k = 4 * r;
        u.x = pack_h2(Win0[j * 96 + k + 0], Wg0[j * 352 + k + 0]);
        u.y = pack_h2(Win0[j * 96 + k + 1], Wg0[j * 352 + k + 1]);
        u.z = pack_h2(Win0[j * 96 + k + 2], Wg0[j * 352 + k + 2]);
        u.w = pack_h2(Win0[j * 96 + k + 3], Wg0[j * 352 + k + 3]);
        gh_s0[r * H + j] = u;
    } else if (r < 24) {                // c0
        int kk = 4 * (r - 16);
        u.x = pack_h2(Win0[j * 96 + 64 + kk + 0], Wg0[j * 352 + 64 + kk + 0]);
        u.y = pack_h2(Win0[j * 96 + 64 + kk + 1], Wg0[j * 352 + 64 + kk + 1]);
        u.z = pack_h2(Win0[j * 96 + 64 + kk + 2], Wg0[j * 352 + 64 + kk + 2]);
        u.w = pack_h2(Win0[j * 96 + 64 + kk + 3], Wg0[j * 352 + 64 + kk + 3]);
        gh_c0[(r - 16) * H + j] = u;
    } else if (r < 88) {                // h0
        int kk = 4 * (r - 24);
        u.x = pack_h2(Wg0[j * 352 + 96 + kk + 0], Wrec0[j * H + kk + 0]);
        u.y = pack_h2(Wg0[j * 352 + 96 + kk + 1], Wrec0[j * H + kk + 1]);
        u.z = pack_h2(Wg0[j * 352 + 96 + kk + 2], Wrec0[j * H + kk + 2]);
        u.w = pack_h2(Wg0[j * 352 + 96 + kk + 3], Wrec0[j * H + kk + 3]);
        gh_h0[(r - 24) * H + j] = u;
    } else if (r < 152) {               // x1
        int kk = 4 * (r - 88);
        u.x = pack_h2(Win1[j * H + kk + 0], Wg1[j * 512 + kk + 0]);
        u.y = pack_h2(Win1[j * H + kk + 1], Wg1[j * 512 + kk + 1]);
        u.z = pack_h2(Win1[j * H + kk + 2], Wg1[j * 512 + kk + 2]);
        u.w = pack_h2(Win1[j * H + kk + 3], Wg1[j * 512 + kk + 3]);
        gh_x1[(r - 88) * H + j] = u;
    } else {                            // h1
        int kk = 4 * (r - 152);
        u.x = pack_h2(Wg1[j * 512 + 256 + kk + 0], Wrec1[j * H + kk + 0]);
        u.y = pack_h2(Wg1[j * 512 + 256 + kk + 1], Wrec1[j * H + kk + 1]);
        u.z = pack_h2(Wg1[j * 512 + 256 + kk + 2], Wrec1[j * H + kk + 2]);
        u.w = pack_h2(Wg1[j * 512 + 256 + kk + 3], Wrec1[j * H + kk + 3]);
        gh_h1[(r - 152) * H + j] = u;
    }
}

// ---- packed fp32x2 helpers ----
__device__ __forceinline__ ull pk2(float a, float b) {
    ull r; asm("mov.b64 %0,{%1,%2};" : "=l"(r) : "f"(a), "f"(b)); return r;
}
__device__ __forceinline__ void up2(ull v, float& a, float& b) {
    asm("mov.b64 {%0,%1},%2;" : "=f"(a), "=f"(b) : "l"(v));
}
__device__ __forceinline__ void fma2(ull& d, ull a, ull b) {
    asm("fma.rn.f32x2 %0,%1,%2,%0;" : "+l"(d) : "l"(a), "l"(b));
}
__device__ __forceinline__ ull add2(ull a, ull b) {
    ull r; asm("add.rn.f32x2 %0,%1,%2;" : "=l"(r) : "l"(a), "l"(b)); return r;
}

// half2 {m1,m2} -> duplicated fp32 pairs {m1,m1}, {m2,m2}.
// The duplicate copy goes through PRMT (alu pipe), and each mov.b64 pairs two
// DISTINCT registers so ptxas can fold it into allocation (no fma-pipe MOVs).
__device__ __forceinline__ void h2dup(unsigned h, ull& w1, ull& w2) {
    asm("{\n\t.reg .b16 lo,hi;\n\t.reg .b32 f1,f2,g1,g2;\n\t"
        "mov.b32 {lo,hi},%2;\n\t"
        "cvt.f32.f16 f1,lo;\n\t"
        "cvt.f32.f16 f2,hi;\n\t"
        "prmt.b32 g1,f1,f1,0x3210;\n\t"    // alu-pipe copy
        "prmt.b32 g2,f2,f2,0x3210;\n\t"    // alu-pipe copy
        "mov.b64 %0,{f1,g1};\n\t"
        "mov.b64 %1,{f2,g2};\n\t}"
        : "=l"(w1), "=l"(w2) : "r"(h));
}

// ---- fast transcendentals (abs err ~1e-7; threshold 1e-3) ----
__device__ __forceinline__ float fast_tanh(float x) {
    float xc = fminf(fmaxf(x, -15.f), 15.f);
    float e  = __expf(2.f * xc);
    return __fdividef(e - 1.f, e + 1.f);
}
__device__ __forceinline__ float fast_sigmoid(float x) {
    return __fdividef(1.f, 1.f + __expf(-x));
}

// ---- hh stored batch-paired: hhp[2*k] = {h0,h1}, hhp[2*k+1] = {h2,h3} ----
__device__ __forceinline__ void st_pair4(ull* dst, float a, float b, float c, float d) {
    *(ulonglong2*)dst = make_ulonglong2(pk2(a, b), pk2(c, d));
}

// acc: {a1_01, a1_23, a2_01, a2_23}: matrix1/matrix2 x batch pairs.
__device__ __forceinline__ void comp4(uint4 w, const ull* __restrict__ hhp,
                                      int k0, ull acc[4]) {
#pragma unroll
    for (int i = 0; i < 4; i++) {
        ull w1d, w2d;
        h2dup((&w.x)[i], w1d, w2d);
        ulonglong2 h = *(const ulonglong2*)(hhp + 2 * (size_t)(k0 + i));  // LDS.128
        fma2(acc[0], w1d, h.x); fma2(acc[1], w1d, h.y);
        fma2(acc[2], w2d, h.x); fma2(acc[3], w2d, h.y);
    }
}

// 16-k-row block: 4x LDG.128 preload / compute
__device__ __forceinline__ void pre4(uint4 w[4], const uint4* __restrict__ g,
                                     int r4, int j) {
#pragma unroll
    for (int i = 0; i < 4; i++) w[i] = g[(size_t)(r4 + i) * H + j];
}
__device__ __forceinline__ void comp16(const uint4 w[4], const ull* __restrict__ hhp,
                                       int k0, ull acc[4]) {
#pragma unroll
    for (int i = 0; i < 4; i++) comp4(w[i], hhp, k0 + 4 * i, acc);
}

// Pipelined matvec over NB 16-row blocks starting at r4base; on exit wA holds
// gnext's block 0 at r4next (chained preload, issued a full block early).
template<int NB>
__device__ __forceinline__ void matvecF(const uint4* __restrict__ g, int r4base,
                                        const uint4* __restrict__ gn, int r4n,
                                        int j, const ull* __restrict__ hhp,
                                        uint4 wA[4], ull acc[4]) {
    uint4 wB[4];
#pragma unroll 1
    for (int b = 0; b < NB; b += 2) {
        pre4(wB, g, r4base + (b + 1) * 4, j);
        comp16(wA, hhp, (r4base + b * 4) * 4, acc);
        if (b + 2 < NB) pre4(wA, g, r4base + (b + 2) * 4, j);
        else            pre4(wA, gn, r4n, j);
        comp16(wB, hhp, (r4base + (b + 1) * 4) * 4, acc);
    }
}

// Block-wide sum of 8 per-thread floats over 512 threads (16 warps).
__device__ __forceinline__ void block_reduce8(float v[8], float* red,
                                              int lane, int warp, float out[8]) {
#pragma unroll
    for (int off = 16; off > 0; off >>= 1) {
#pragma unroll
        for (int i = 0; i < 8; i++)
            v[i] += __shfl_xor_sync(0xffffffffu, v[i], off);
    }
    if (lane == 0) {
#pragma unroll
        for (int i = 0; i < 8; i++) red[warp * 8 + i] = v[i];
    }
    __syncthreads();
#pragma unroll
    for (int i = 0; i < 8; i++) out[i] = 0.f;
#pragma unroll
    for (int w = 0; w < 16; w++) {
#pragma unroll
        for (int i = 0; i < 8; i++) out[i] += red[w * 8 + i];
    }
    __syncthreads();
}

// One full layer at one timestep: fused proj + RK4 + LayerNorm + tanh.
// Entry (pre-barrier): xvec ready, hh2[0] = h-state (half0-written), wA = gp blk 0.
// Exit: h updated (half 0 only), wA = gn block 0 at r4n.
template<int NBP>
__device__ __forceinline__ void layer_fused(
    const uint4* __restrict__ gp, int r4p,      // proj matrix
    const uint4* __restrict__ gs, int r4s,      // stage (recurrent) matrix
    const uint4* __restrict__ gn, int r4n,      // next phase's proj matrix
    const ull* __restrict__ xvec,
    ull (*hh2)[2 * H], ull (*part)[256], ull (*partP)[4][256], float* red,
    int jj, int half, int lane, int warp,
    float h[4], const ull pinit[4],
    float invtau, float lng, float lnb, uint4 wA[4]) {

    __syncthreads();   // A: xvec + hh2[0] + wA ready
    // ---- proj matvec (matrix1 -> pin, matrix2 -> pg) ----
    ull P[4];
    if (half == 0) { P[0] = pinit[0]; P[1] = pinit[1]; P[2] = pinit[2]; P[3] = pinit[3]; }
    else           { P[0] = P[1] = P[2] = P[3] = 0ull; }
    matvecF<NBP>(gp, r4p, gs, r4s, jj, xvec, wA, P);
    partP[half][0][jj] = P[0]; partP[half][1][jj] = P[1];
    partP[half][2][jj] = P[2]; partP[half][3][jj] = P[3];

    // ---- stage-0 matvec, no intervening barrier (hh2[0] set at prev epilogue) ----
    ull S[4] = {0ull, 0ull, 0ull, 0ull};
    matvecF<8>(gs, r4s, gs, r4s, jj, hh2[0], wA, S);
    if (half) { part[0][jj] = S[0]; part[1][jj] = S[1];
                part[2][jj] = S[2]; part[3][jj] = S[3]; }
    __syncthreads();   // B: both partial sets visible

    float pin[4], pg[4], hs[4], kacc[4];
    if (half == 0) {
        ull p01 = add2(partP[0][0][jj], partP[1][0][jj]);
        ull p23 = add2(partP[0][1][jj], partP[1][1][jj]);
        ull g01 = add2(partP[0][2][jj], partP[1][2][jj]);
        ull g23 = add2(partP[0][3][jj], partP[1][3][jj]);
        up2(p01, pin[0], pin[1]); up2(p23, pin[2], pin[3]);
        up2(g01, pg[0],  pg[1]);  up2(g23, pg[2],  pg[3]);
        ull ag01 = add2(add2(S[0], part[0][jj]), g01);
        ull ag23 = add2(add2(S[1], part[1][jj]), g23);
        ull ar01 = add2(S[2], part[2][jj]);
        ull ar23 = add2(S[3], part[3][jj]);
        float ag[4], ar[4];
        up2(ag01, ag[0], ag[1]); up2(ag23, ag[2], ag[3]);
        up2(ar01, ar[0], ar[1]); up2(ar23, ar[2], ar[3]);
#pragma unroll
        for (int b = 0; b < 4; b++) {           // s = 0 epilogue
            float tg = fast_tanh(ag[b]);
            float gg = fast_sigmoid(tg);
            float kb = pin[b] - h[b] * invtau + gg * ar[b];
            kacc[b]  = kb;
            hs[b]    = h[b] + 0.5f * kb;
        }
        st_pair4(&hh2[1][2 * jj], hs[0], hs[1], hs[2], hs[3]);
    }

    // ---- stages 1..3 ----
#pragma unroll 1
    for (int s = 1; s < 4; s++) {
        __syncthreads();   // A_s: hh2[s&1] + wA ready
        ull acc[4];
        if (half == 0) { acc[0] = pk2(pg[0], pg[1]); acc[1] = pk2(pg[2], pg[3]); }
        else           { acc[0] = 0ull;              acc[1] = 0ull; }
        acc[2] = 0ull; acc[3] = 0ull;
        const uint4* nx = (s < 3) ? gs : gn;
        int r4x = (s < 3) ? r4s : r4n;
        matvecF<8>(gs, r4s, nx, r4x, jj, hh2[s & 1], wA, acc);
        if (half) { part[0][jj] = acc[0]; part[1][jj] = acc[1];
                    part[2][jj] = acc[2]; part[3][jj] = acc[3]; }
        __syncthreads();   // B_s
        if (half == 0) {
            acc[0] = add2(acc[0], part[0][jj]); acc[1] = add2(acc[1], part[1][jj]);
            acc[2] = add2(acc[2], part[2][jj]); acc[3] = add2(acc[3], part[3][jj]);
            float ag[4], ar[4];
            up2(acc[0], ag[0], ag[1]); up2(acc[1], ag[2], ag[3]);
            up2(acc[2], ar[0], ar[1]); up2(acc[3], ar[2], ar[3]);
            float cn  = (s < 2) ? 0.5f : 1.0f;
            float wks = (s == 1 || s == 2) ? 2.0f : 1.0f;
#pragma unroll
            for (int b = 0; b < 4; b++) {
                float tg = fast_tanh(ag[b]);
                float gg = fast_sigmoid(tg);
                float kb = pin[b] - hs[b] * invtau + gg * ar[b];
                kacc[b] += wks * kb;
                if (s < 3) hs[b] = h[b] + cn * kb;
            }
            if (s < 3)
                st_pair4(&hh2[(s + 1) & 1][2 * jj], hs[0], hs[1], hs[2], hs[3]);
        }
    }

    // ---- LayerNorm + tanh ----
    float v8[8];
    if (half == 0) {
#pragma unroll
        for (int b = 0; b < 4; b++) {
            float hnb = h[b] + kacc[b] * (1.f / 6.f);
            hs[b]     = hnb;
            v8[b]     = hnb;
            v8[4 + b] = hnb * hnb;
        }
    } else {
#pragma unroll
        for (int i = 0; i < 8; i++) v8[i] = 0.f;
    }
    float o8[8];
    block_reduce8(v8, red, lane, warp, o8);
    if (half == 0) {
#pragma unroll
        for (int b = 0; b < 4; b++) {
            float mu   = o8[b] * (1.f / (float)H);
            float var  = o8[4 + b] * (1.f / (float)H) - mu * mu;
            float rstd = rsqrtf(var + LN_EPS);
            h[b] = fast_tanh((hs[b] - mu) * rstd * lng + lnb);   // clip is a no-op
        }
    }
}

__global__ __launch_bounds__(512, 1)
void ltc_main(const float* __restrict__ seq,  const float* __restrict__ ctx,
              const float* __restrict__ tau0, const float* __restrict__ bg0,
              const float* __restrict__ lng0, const float* __restrict__ lnb0,
              const float* __restrict__ tau1, const float* __restrict__ bg1,
              const float* __restrict__ lng1, const float* __restrict__ lnb1,
              const float* __restrict__ cW1,  const float* __restrict__ cb1,
              const float* __restrict__ cW2,  const float* __restrict__ cb2,
              float* __restrict__ out) {
    __shared__ __align__(16) ull hh2[2][2 * H];      // stage vec, batch-paired
    __shared__ __align__(16) ull xinp[2 * H];        // layer-1 input
    __shared__ __align__(16) ull xsp[2 * FS];        // seq features (ctx at init)
    __shared__ __align__(16) ull part[4][256];       // stage partials (half 1)
    __shared__ __align__(16) ull partP[2][4][256];   // proj partials (both halves)
    __shared__ __align__(16) ull cwg[4][256];        // ctx-folded {cwin, cg}
    __shared__ float red[128];

    int tid  = threadIdx.x;
    int jj   = tid & 255;          // neuron
    int half = tid >> 8;           // k-half
    int lane = tid & 31, warp = tid >> 5;
    int b0   = blockIdx.x * 4;

    float invt0 = 1.f / (log1pf(expf(tau0[jj])) + 1.f);
    float invt1 = 1.f / (log1pf(expf(tau1[jj])) + 1.f);
    float lng0v = lng0[jj], lnb0v = lnb0[jj];
    float lng1v = lng1[jj], lnb1v = lnb1[jj];
    float rbg1  = bg1[jj];

    // ---- ctx contributions to layer-0 pre-activations (constant over t) ----
    if (tid < FC) {
        float c0 = ctx[(b0 + 0) * FC + tid], c1 = ctx[(b0 + 1) * FC + tid];
        float c2 = ctx[(b0 + 2) * FC + tid], c3 = ctx[(b0 + 3) * FC + tid];
        st_pair4(&xsp[2 * tid], c0, c1, c2, c3);
    }
    __syncthreads();
    if (half == 0) {
        ull acc[4];
        float bv = bg0[jj];
        acc[0] = 0ull; acc[1] = 0ull;
        acc[2] = pk2(bv, bv); acc[3] = acc[2];
#pragma unroll
        for (int r4 = 0; r4 < FC / 4; r4++) {
            uint4 w = gh_c0[r4 * H + jj];
            comp4(w, xsp, 4 * r4, acc);
        }
        cwg[0][jj] = acc[0]; cwg[1][jj] = acc[1];
        cwg[2][jj] = acc[2]; cwg[3][jj] = acc[3];
        st_pair4(&hh2[0][2 * jj], 0.f, 0.f, 0.f, 0.f);   // h0 init
    }
    __syncthreads();

    float h0r[4] = {0.f, 0.f, 0.f, 0.f};
    float h1r[4] = {0.f, 0.f, 0.f, 0.f};

    const int r4S = half * 8;    // proj0: FS=64 rows -> 16 r4; half = 8
    const int r4H = half * 32;   // H matvecs: 256 rows -> 64 r4; half = 32

    ull pin0[4] = {cwg[0][jj], cwg[1][jj], cwg[2][jj], cwg[3][jj]};
    ull pin1[4] = {0ull, 0ull, pk2(rbg1, rbg1), pk2(rbg1, rbg1)};

    uint4 wA[4];
    pre4(wA, gh_s0, r4S, jj);

#pragma unroll 1
    for (int t = 0; t < Tsz; t++) {
        if (tid < FS) {
            size_t o = (size_t)t * FS + tid;
            float s0v = seq[(size_t)(b0 + 0) * Tsz * FS + o];
            float s1v = seq[(size_t)(b0 + 1) * Tsz * FS + o];
            float s2v = seq[(size_t)(b0 + 2) * Tsz * FS + o];
            float s3v = seq[(size_t)(b0 + 3) * Tsz * FS + o];
            st_pair4(&xsp[2 * tid], s0v, s1v, s2v, s3v);
        }

        // ---- layer 0 (hh2[0] = h0, written at previous epilogue) ----
        layer_fused<2>(gh_s0, r4S, gh_h0, r4H, gh_x1, r4H, xsp,
                       hh2, part, partP, red, jj, half, lane, warp,
                       h0r, pin0, invt0, lng0v, lnb0v, wA);

        // hand layer-0 output to layer 1; publish h1 state for layer 1
        if (half == 0) {
            st_pair4(&xinp[2 * jj], h0r[0], h0r[1], h0r[2], h0r[3]);
            st_pair4(&hh2[0][2 * jj], h1r[0], h1r[1], h1r[2], h1r[3]);
        }

        // ---- layer 1 ----
        layer_fused<8>(gh_x1, r4H, gh_h1, r4H, gh_s0, r4S, xinp,
                       hh2, part, partP, red, jj, half, lane, warp,
                       h1r, pin1, invt1, lng1v, lnb1v, wA);

        // publish h0 state for next timestep's layer 0
        if (half == 0)
            st_pair4(&hh2[0][2 * jj], h0r[0], h0r[1], h0r[2], h0r[3]);
    }

    // ---- head: out = relu(h1 @ cW1.T + cb1) @ cW2.T + cb2 ----
    if (half == 0)
        st_pair4(&xinp[2 * jj], h1r[0], h1r[1], h1r[2], h1r[3]);
    __syncthreads();

    float v8[8];
#pragma unroll
    for (int i = 0; i < 8; i++) v8[i] = 0.f;
    if (tid < 128) {
        float acc4[4];
        float bb = cb1[tid];
#pragma unroll
        for (int b = 0; b < 4; b++) acc4[b] = bb;
        const float* xf = (const float*)xinp;   // batch-paired: x_b = xf[4*k + b]
#pragma unroll 8
        for (int k = 0; k < H; k++) {
            float w = cW1[tid * H + k];
            acc4[0] += w * xf[4 * k + 0];
            acc4[1] += w * xf[4 * k + 1];
            acc4[2] += w * xf[4 * k + 2];
            acc4[3] += w * xf[4 * k + 3];
        }
        float w2 = cW2[tid];
#pragma unroll
        for (int b = 0; b < 4; b++) v8[b] = fmaxf(acc4[b], 0.f) * w2;
    }
    float o8[8];
    block_reduce8(v8, red, lane, warp, o8);
    if (tid < 4) out[b0 + tid] = o8[tid] + cb2[0];
}

extern "C" void kernel_launch(void* const* d_in, const int* in_sizes, int n_in,
                              void* d_out, int out_size) {
    const float* seq   = (const float*)d_in[0];
    const float* ctx   = (const float*)d_in[1];
    const float* tau0  = (const float*)d_in[2];
    const float* Win0  = (const float*)d_in[3];
    const float* Wrec0 = (const float*)d_in[4];
    const float* Wg0   = (const float*)d_in[5];
    const float* bg0   = (const float*)d_in[6];
    const float* lng0  = (const float*)d_in[7];
    const float* lnb0  = (const float*)d_in[8];
    const float* tau1  = (const float*)d_in[9];
    const float* Win1  = (const float*)d_in[10];
    const float* Wrec1 = (const float*)d_in[11];
    const float* Wg1   = (const float*)d_in[12];
    const float* bg1   = (const float*)d_in[13];
    const float* lng1  = (const float*)d_in[14];
    const float* lnb1  = (const float*)d_in[15];
    const float* cW1   = (const float*)d_in[16];
    const float* cb1   = (const float*)d_in[17];
    const float* cW2   = (const float*)d_in[18];
    const float* cb2   = (const float*)d_in[19];
    float* out = (float*)d_out;

    setup_kernel<<<216, 256>>>(Win0, Wrec0, Wg0, Win1, Wrec1, Wg1);
    ltc_main<<<128, 512>>>(seq, ctx, tau0, bg0, lng0, lnb0,
                           tau1, bg1, lng1, lnb1,
                           cW1, cb1, cW2, cb2, out);
}

// round 13
// speedup vs baseline: 2.1377x; 2.1377x over previous
#include <cuda_runtime.h>
#include <cuda_fp16.h>
#include <math.h>

#define Tsz 512
#define FS 64
#define FC 32
#define H 256
#define LN_EPS 1e-5f

// ============================================================================
// Weight storage: pre-swizzled mma.m16n8k16 A-fragments (fp16).
// Fragment index: idx = kt*512 + w*32 + lane  (uint4 = 8 halves = full a-frag)
//   lane: r = lane>>2, c = (lane&3)*2
//   a0={A[r][c],A[r][c+1]}  a1={A[r+8][c],...}  a2={A[r][c+8],...}  a3={A[r+8][c+8],...}
//   where A[j][k] is the j-th neuron row, k-th input column of the tile
//   (j = 16*w + r offset, k = 16*kt + c offset).
// ============================================================================
__device__ uint4 gA_p0a[4 * 512];    // Win0 seq part  (K=64)
__device__ uint4 gA_p0b[4 * 512];    // Wg0  seq part
__device__ uint4 gA_c0a[2 * 512];    // Win0 ctx part  (K=32)
__device__ uint4 gA_c0b[2 * 512];    // Wg0  ctx part
__device__ uint4 gA_h0a[16 * 512];   // Wg0  h part    (K=256)
__device__ uint4 gA_h0b[16 * 512];   // Wrec0
__device__ uint4 gA_x1a[16 * 512];   // Win1
__device__ uint4 gA_x1b[16 * 512];   // Wg1 x part
__device__ uint4 gA_h1a[16 * 512];   // Wg1 h part
__device__ uint4 gA_h1b[16 * 512];   // Wrec1

__device__ __forceinline__ unsigned pack_h2(float a, float b) {
    __half2 h = __floats2half2_rn(a, b);   // a -> lo, b -> hi
    return *reinterpret_cast<unsigned*>(&h);
}

__global__ void setup_kernel(const float* __restrict__ Win0,
                             const float* __restrict__ Wrec0,
                             const float* __restrict__ Wg0,
                             const float* __restrict__ Win1,
                             const float* __restrict__ Wrec1,
                             const float* __restrict__ Wg1) {
    int idx = blockIdx.x * 512 + threadIdx.x;   // 0 .. 55295
    const float* src; int jstr, koff; uint4* dst; int base;
    if      (idx <  2048) { dst = gA_p0a; base = 0;     src = Win0;  jstr = 96;  koff = 0;   }
    else if (idx <  4096) { dst = gA_p0b; base = 2048;  src = Wg0;   jstr = 352; koff = 0;   }
    else if (idx <  5120) { dst = gA_c0a; base = 4096;  src = Win0;  jstr = 96;  koff = 64;  }
    else if (idx <  6144) { dst = gA_c0b; base = 5120;  src = Wg0;   jstr = 352; koff = 64;  }
    else if (idx < 14336) { dst = gA_h0a; base = 6144;  src = Wg0;   jstr = 352; koff = 96;  }
    else if (idx < 22528) { dst = gA_h0b; base = 14336; src = Wrec0; jstr = 256; koff = 0;   }
    else if (idx < 30720) { dst = gA_x1a; base = 22528; src = Win1;  jstr = 256; koff = 0;   }
    else if (idx < 38912) { dst = gA_x1b; base = 30720; src = Wg1;   jstr = 512; koff = 0;   }
    else if (idx < 47104) { dst = gA_h1a; base = 38912; src = Wg1;   jstr = 512; koff = 256; }
    else                  { dst = gA_h1b; base = 47104; src = Wrec1; jstr = 256; koff = 0;   }
    int li = idx - base;
    int lane = li & 31, w = (li >> 5) & 15, kt = li >> 9;
    int r = lane >> 2, c = (lane & 3) * 2;
    int j0 = w * 16 + r, k0 = kt * 16 + c;
    const float* r0 = src + (size_t)j0 * jstr + koff;
    const float* r8 = src + (size_t)(j0 + 8) * jstr + koff;
    uint4 u;
    u.x = pack_h2(r0[k0],     r0[k0 + 1]);
    u.y = pack_h2(r8[k0],     r8[k0 + 1]);
    u.z = pack_h2(r0[k0 + 8], r0[k0 + 9]);
    u.w = pack_h2(r8[k0 + 8], r8[k0 + 9]);
    dst[li] = u;
}

// ============================================================================
// Device helpers
// ============================================================================
__device__ __forceinline__ void mma16816(float c[4], uint4 a, unsigned b0, unsigned b1) {
    asm volatile(
        "mma.sync.aligned.m16n8k16.row.col.f32.f16.f16.f32 "
        "{%0,%1,%2,%3},{%4,%5,%6,%7},{%8,%9},{%0,%1,%2,%3};"
        : "+f"(c[0]), "+f"(c[1]), "+f"(c[2]), "+f"(c[3])
        : "r"(a.x), "r"(a.y), "r"(a.z), "r"(a.w), "r"(b0), "r"(b1));
}

__device__ __forceinline__ float fast_tanh(float x) {
    float xc = fminf(fmaxf(x, -15.f), 15.f);
    float e  = __expf(2.f * xc);
    return __fdividef(e - 1.f, e + 1.f);
}
__device__ __forceinline__ float fast_sigmoid(float x) {
    return __fdividef(1.f, 1.f + __expf(-x));
}

// Dual-matrix MMA sweep over NKT 16-wide k-tiles. B hi/lo split (fp32-exact
// state). c1 += M1 x, c2 += M2 x. B layout: [n][STR] halves, k contiguous.
template<int NKT, int STR>
__device__ __forceinline__ void sweep2(const uint4* __restrict__ ga,
                                       const uint4* __restrict__ gb,
                                       const __half* __restrict__ Bhi,
                                       const __half* __restrict__ Blo,
                                       int w, int lane,
                                       float c1[4], float c2[4]) {
    float d1[4] = {0.f, 0.f, 0.f, 0.f}, d2[4] = {0.f, 0.f, 0.f, 0.f};
    const int n  = lane >> 2;
    const int k0 = (lane & 3) * 2;
    const __half* bh = Bhi + n * STR + k0;
    const __half* bl = Blo + n * STR + k0;
    const int base = w * 32 + lane;
#pragma unroll 4
    for (int kt = 0; kt < NKT; kt++) {
        uint4 a1 = ga[kt * 512 + base];
        uint4 a2 = gb[kt * 512 + base];
        unsigned bh0 = *(const unsigned*)(bh + kt * 16);
        unsigned bh1 = *(const unsigned*)(bh + kt * 16 + 8);
        unsigned bl0 = *(const unsigned*)(bl + kt * 16);
        unsigned bl1 = *(const unsigned*)(bl + kt * 16 + 8);
        mma16816(c1, a1, bh0, bh1);
        mma16816(c2, a2, bh0, bh1);
        mma16816(d1, a1, bl0, bl1);
        mma16816(d2, a2, bl0, bl1);
    }
#pragma unroll
    for (int i = 0; i < 4; i++) { c1[i] += d1[i]; c2[i] += d2[i]; }
}

// Write a C-fragment-layout vector v (rows j, batch cols) into a hi/lo split
// B array ([n][264] halves). Only lanes owning real batch cols (n<4) write.
__device__ __forceinline__ void writeB(__half* hi, __half* lo, int lane, int w,
                                       const float v[4]) {
    if ((lane & 3) < 2) {
        int n0 = (lane & 3) * 2;
        int j  = w * 16 + (lane >> 2);
#pragma unroll
        for (int e = 0; e < 4; e++) {
            int n  = n0 + (e & 1);
            int jj = j + (e >> 1) * 8;
            float vv = v[e];
            __half hv = __float2half_rn(vv);
            hi[n * 264 + jj] = hv;
            lo[n * 264 + jj] = __float2half_rn(vv - __half2float(hv));
        }
    }
}

struct __align__(16) SmemT {
    __half stA_hi[8][264], stA_lo[8][264];   // stage double-buffer A
    __half stB_hi[8][264], stB_lo[8][264];   // stage double-buffer B
    __half h0_hi[8][264],  h0_lo[8][264];    // layer-0 state (also layer-1 input)
    __half h1_hi[8][264],  h1_lo[8][264];    // layer-1 state
    __half xs_hi[8][72],   xs_lo[8][72];     // seq features at t (K=64)
    __half cx_hi[8][40],   cx_lo[8][40];     // ctx features (K=32)
    float  red[256];
    float  stats[16];
};

// One layer at one timestep: proj + 4 RK4 stages + LayerNorm + tanh.
// All quantities fragment-resident. Entry assumes a prior __syncthreads covers
// x arrays, hB arrays, and any stage-buffer reuse.
template<int NKTP, int STRP>
__device__ __forceinline__ void layer_run(
    const uint4* __restrict__ gpa, const uint4* __restrict__ gpb,
    const __half* __restrict__ xhi, const __half* __restrict__ xlo,
    const uint4* __restrict__ gsa, const uint4* __restrict__ gsb,
    __half* __restrict__ hBhi, __half* __restrict__ hBlo,
    SmemT& sm, int tid, int w, int lane,
    const float pinI[4], const float pgI[4],
    const float it0, const float it1,
    const float lg0v, const float lg1v, const float lb0v, const float lb1v,
    float h[4]) {

    float pin[4], pg[4];
#pragma unroll
    for (int i = 0; i < 4; i++) { pin[i] = pinI[i]; pg[i] = pgI[i]; }
    sweep2<NKTP, STRP>(gpa, gpb, xhi, xlo, w, lane, pin, pg);

    float cg[4] = {0.f, 0.f, 0.f, 0.f}, cr[4] = {0.f, 0.f, 0.f, 0.f};
    sweep2<16, 264>(gsa, gsb, hBhi, hBlo, w, lane, cg, cr);

    float hs[4], kacc[4];
#pragma unroll
    for (int e = 0; e < 4; e++) {                     // stage 0 epilogue
        float gg = fast_sigmoid(fast_tanh(pg[e] + cg[e]));
        float kb = pin[e] - h[e] * ((e < 2) ? it0 : it1) + gg * cr[e];
        kacc[e] = kb;
        hs[e]   = h[e] + 0.5f * kb;
    }
    writeB(&sm.stA_hi[0][0], &sm.stA_lo[0][0], lane, w, hs);

    // stage 1
    __syncthreads();
#pragma unroll
    for (int i = 0; i < 4; i++) { cg[i] = 0.f; cr[i] = 0.f; }
    sweep2<16, 264>(gsa, gsb, &sm.stA_hi[0][0], &sm.stA_lo[0][0], w, lane, cg, cr);
#pragma unroll
    for (int e = 0; e < 4; e++) {
        float gg = fast_sigmoid(fast_tanh(pg[e] + cg[e]));
        float kb = pin[e] - hs[e] * ((e < 2) ? it0 : it1) + gg * cr[e];
        kacc[e] += 2.f * kb;
        hs[e]    = h[e] + 0.5f * kb;
    }
    writeB(&sm.stB_hi[0][0], &sm.stB_lo[0][0], lane, w, hs);

    // stage 2
    __syncthreads();
#pragma unroll
    for (int i = 0; i < 4; i++) { cg[i] = 0.f; cr[i] = 0.f; }
    sweep2<16, 264>(gsa, gsb, &sm.stB_hi[0][0], &sm.stB_lo[0][0], w, lane, cg, cr);
#pragma unroll
    for (int e = 0; e < 4; e++) {
        float gg = fast_sigmoid(fast_tanh(pg[e] + cg[e]));
        float kb = pin[e] - hs[e] * ((e < 2) ? it0 : it1) + gg * cr[e];
        kacc[e] += 2.f * kb;
        hs[e]    = h[e] + kb;
    }
    writeB(&sm.stA_hi[0][0], &sm.stA_lo[0][0], lane, w, hs);

    // stage 3
    __syncthreads();
#pragma unroll
    for (int i = 0; i < 4; i++) { cg[i] = 0.f; cr[i] = 0.f; }
    sweep2<16, 264>(gsa, gsb, &sm.stA_hi[0][0], &sm.stA_lo[0][0], w, lane, cg, cr);
    float hn[4];
#pragma unroll
    for (int e = 0; e < 4; e++) {
        float gg = fast_sigmoid(fast_tanh(pg[e] + cg[e]));
        float kb = pin[e] - hs[e] * ((e < 2) ? it0 : it1) + gg * cr[e];
        kacc[e] += kb;
        hn[e]    = h[e] + kacc[e] * (1.f / 6.f);
    }

    // LayerNorm over j (256) per batch col
    float s0 = hn[0] + hn[2], s1 = hn[1] + hn[3];
    float q0 = hn[0] * hn[0] + hn[2] * hn[2];
    float q1 = hn[1] * hn[1] + hn[3] * hn[3];
#pragma unroll
    for (int off = 4; off <= 16; off <<= 1) {
        s0 += __shfl_xor_sync(0xffffffffu, s0, off);
        s1 += __shfl_xor_sync(0xffffffffu, s1, off);
        q0 += __shfl_xor_sync(0xffffffffu, q0, off);
        q1 += __shfl_xor_sync(0xffffffffu, q1, off);
    }
    if (lane < 4) {
        float* rp = sm.red + (w * 4 + lane) * 4;
        rp[0] = s0; rp[1] = s1; rp[2] = q0; rp[3] = q1;
    }
    __syncthreads();
    if (tid < 16) {
        float tsum = 0.f;
#pragma unroll
        for (int ww = 0; ww < 16; ww++)
            tsum += sm.red[(ww * 4 + (tid >> 2)) * 4 + (tid & 3)];
        sm.stats[tid] = tsum;
    }
    __syncthreads();
    int gq = lane & 3;
    float mu0 = sm.stats[gq * 4 + 0] * (1.f / (float)H);
    float mu1 = sm.stats[gq * 4 + 1] * (1.f / (float)H);
    float rs0 = rsqrtf(sm.stats[gq * 4 + 2] * (1.f / (float)H) - mu0 * mu0 + LN_EPS);
    float rs1 = rsqrtf(sm.stats[gq * 4 + 3] * (1.f / (float)H) - mu1 * mu1 + LN_EPS);
#pragma unroll
    for (int e = 0; e < 4; e++) {
        float mu = (e & 1) ? mu1 : mu0;
        float rs = (e & 1) ? rs1 : rs0;
        float lg = (e < 2) ? lg0v : lg1v;
        float lb = (e < 2) ? lb0v : lb1v;
        h[e] = fast_tanh((hn[e] - mu) * rs * lg + lb);   // clip is a no-op
    }
    writeB(hBhi, hBlo, lane, w, h);
}

__global__ __launch_bounds__(512, 1)
void ltc_main(const float* __restrict__ seq,  const float* __restrict__ ctx,
              const float* __restrict__ tau0, const float* __restrict__ bg0,
              const float* __restrict__ lng0, const float* __restrict__ lnb0,
              const float* __restrict__ tau1, const float* __restrict__ bg1,
              const float* __restrict__ lng1, const float* __restrict__ lnb1,
              const float* __restrict__ cW1,  const float* __restrict__ cb1,
              const float* __restrict__ cW2,  const float* __restrict__ cb2,
              float* __restrict__ out) {
    __shared__ SmemT sm;
    int tid  = threadIdx.x;
    int lane = tid & 31, w = tid >> 5;
    int b0   = blockIdx.x * 4;

    // zero SMEM (pads must be finite; h-state starts at 0)
    for (int i = tid; i < (int)(sizeof(SmemT) / 4); i += 512)
        ((int*)&sm)[i] = 0;

    int r  = lane >> 2;
    int j0 = w * 16 + r, j8 = j0 + 8;

    float it0a = 1.f / (log1pf(expf(tau0[j0])) + 1.f);
    float it0b = 1.f / (log1pf(expf(tau0[j8])) + 1.f);
    float it1a = 1.f / (log1pf(expf(tau1[j0])) + 1.f);
    float it1b = 1.f / (log1pf(expf(tau1[j8])) + 1.f);
    float lg0a = lng0[j0], lg0b = lng0[j8], lb0a = lnb0[j0], lb0b = lnb0[j8];
    float lg1a = lng1[j0], lg1b = lng1[j8], lb1a = lnb1[j0], lb1b = lnb1[j8];
    float bg1a = bg1[j0],  bg1b = bg1[j8];
    float bg0a = bg0[j0],  bg0b = bg0[j8];

    __syncthreads();   // zero done

    // ---- ctx features -> cx arrays (hi/lo) ----
    if (tid < FC) {
#pragma unroll
        for (int n = 0; n < 4; n++) {
            float v = ctx[(size_t)(b0 + n) * FC + tid];
            __half hv = __float2half_rn(v);
            sm.cx_hi[n][tid] = hv;
            sm.cx_lo[n][tid] = __float2half_rn(v - __half2float(hv));
        }
    }
    __syncthreads();

    // ---- ctx-folded pre-activation fragments (constant over t) ----
    float cwinF[4] = {0.f, 0.f, 0.f, 0.f}, cgF[4] = {0.f, 0.f, 0.f, 0.f};
    sweep2<2, 40>(gA_c0a, gA_c0b, &sm.cx_hi[0][0], &sm.cx_lo[0][0], w, lane, cwinF, cgF);
    cgF[0] += bg0a; cgF[1] += bg0a; cgF[2] += bg0b; cgF[3] += bg0b;

    float pin1I[4] = {0.f, 0.f, 0.f, 0.f};
    float pg1I[4]  = {bg1a, bg1a, bg1b, bg1b};

    float h0f[4] = {0.f, 0.f, 0.f, 0.f};
    float h1f[4] = {0.f, 0.f, 0.f, 0.f};

#pragma unroll 1
    for (int t = 0; t < Tsz; t++) {
        // seq features for this t (hi/lo split)
        if (tid < FS) {
            size_t o = (size_t)t * FS + tid;
#pragma unroll
            for (int n = 0; n < 4; n++) {
                float v = seq[(size_t)(b0 + n) * Tsz * FS + o];
                __half hv = __float2half_rn(v);
                sm.xs_hi[n][tid] = hv;
                sm.xs_lo[n][tid] = __float2half_rn(v - __half2float(hv));
            }
        }
        __syncthreads();   // xs ready; h1B (prev t) ready; stage bufs free

        // ---- layer 0 ----
        layer_run<4, 72>(gA_p0a, gA_p0b, &sm.xs_hi[0][0], &sm.xs_lo[0][0],
                         gA_h0a, gA_h0b, &sm.h0_hi[0][0], &sm.h0_lo[0][0],
                         sm, tid, w, lane, cwinF, cgF,
                         it0a, it0b, lg0a, lg0b, lb0a, lb0b, h0f);

        __syncthreads();   // h0B ready for layer-1 proj

        // ---- layer 1 (input = h0B) ----
        layer_run<16, 264>(gA_x1a, gA_x1b, &sm.h0_hi[0][0], &sm.h0_lo[0][0],
                           gA_h1a, gA_h1b, &sm.h1_hi[0][0], &sm.h1_lo[0][0],
                           sm, tid, w, lane, pin1I, pg1I,
                           it1a, it1b, lg1a, lg1b, lb1a, lb1b, h1f);
        // next-t top barrier covers h1B write
    }

    // ---- head: out = relu(h1 @ cW1.T + cb1) @ cW2.T + cb2 ----
    __syncthreads();
    float* xf = (float*)&sm.stA_hi[0][0];   // 1024-float scratch
    if (tid < 256) {
#pragma unroll
        for (int n = 0; n < 4; n++)
            xf[n * 256 + tid] =
                __half2float(sm.h1_hi[n][tid]) + __half2float(sm.h1_lo[n][tid]);
    }
    __syncthreads();

    float p[4] = {0.f, 0.f, 0.f, 0.f};
    if (tid < 128) {
        float acc[4];
        float bb = cb1[tid];
#pragma unroll
        for (int b = 0; b < 4; b++) acc[b] = bb;
#pragma unroll 8
        for (int k = 0; k < H; k++) {
            float wv = cW1[tid * H + k];
            acc[0] += wv * xf[k];
            acc[1] += wv * xf[256 + k];
            acc[2] += wv * xf[512 + k];
            acc[3] += wv * xf[768 + k];
        }
        float w2 = cW2[tid];
#pragma unroll
        for (int b = 0; b < 4; b++) p[b] = fmaxf(acc[b], 0.f) * w2;
    }
    // block-wide sum of p over 512 threads
#pragma unroll
    for (int off = 16; off > 0; off >>= 1) {
#pragma unroll
        for (int b = 0; b < 4; b++)
            p[b] += __shfl_xor_sync(0xffffffffu, p[b], off);
    }
    if (lane == 0) {
#pragma unroll
        for (int b = 0; b < 4; b++) sm.red[w * 4 + b] = p[b];
    }
    __syncthreads();
    if (tid < 4) {
        float o = 0.f;
#pragma unroll
        for (int ww = 0; ww < 16; ww++) o += sm.red[ww * 4 + tid];
        out[b0 + tid] = o + cb2[0];
    }
}

extern "C" void kernel_launch(void* const* d_in, const int* in_sizes, int n_in,
                              void* d_out, int out_size) {
    const float* seq   = (const float*)d_in[0];
    const float* ctx   = (const float*)d_in[1];
    const float* tau0  = (const float*)d_in[2];
    const float* Win0  = (const float*)d_in[3];
    const float* Wrec0 = (const float*)d_in[4];
    const float* Wg0   = (const float*)d_in[5];
    const float* bg0   = (const float*)d_in[6];
    const float* lng0  = (const float*)d_in[7];
    const float* lnb0  = (const float*)d_in[8];
    const float* tau1  = (const float*)d_in[9];
    const float* Win1  = (const float*)d_in[10];
    const float* Wrec1 = (const float*)d_in[11];
    const float* Wg1   = (const float*)d_in[12];
    const float* bg1   = (const float*)d_in[13];
    const float* lng1  = (const float*)d_in[14];
    const float* lnb1  = (const float*)d_in[15];
    const float* cW1   = (const float*)d_in[16];
    const float* cb1   = (const float*)d_in[17];
    const float* cW2   = (const float*)d_in[18];
    const float* cb2   = (const float*)d_in[19];
    float* out = (float*)d_out;

    setup_kernel<<<108, 512>>>(Win0, Wrec0, Wg0, Win1, Wrec1, Wg1);
    ltc_main<<<128, 512>>>(seq, ctx, tau0, bg0, lng0, lnb0,
                           tau1, bg1, lng1, lnb1,
                           cW1, cb1, cW2, cb2, out);
}

// round 15
// speedup vs baseline: 2.7017x; 1.2638x over previous
#include <cuda_runtime.h>
#include <cuda_fp16.h>
#include <math.h>

#define Tsz 512
#define FS 64
#define FC 32
#define H 256
#define LN_EPS 1e-5f

// ============================================================================
// Weight storage: pre-swizzled mma.m16n8k16 A-fragments (fp16).
// idx = kt*512 + w*32 + lane (uint4 = full 8-half a-frag).
// ============================================================================
__device__ uint4 gA_p0a[4 * 512];    // Win0 seq part  (K=64)
__device__ uint4 gA_p0b[4 * 512];    // Wg0  seq part
__device__ uint4 gA_c0a[2 * 512];    // Win0 ctx part  (K=32)
__device__ uint4 gA_c0b[2 * 512];    // Wg0  ctx part
__device__ uint4 gA_h0a[16 * 512];   // Wg0  h part    (K=256)
__device__ uint4 gA_h0b[16 * 512];   // Wrec0
__device__ uint4 gA_x1a[16 * 512];   // Win1
__device__ uint4 gA_x1b[16 * 512];   // Wg1 x part
__device__ uint4 gA_h1a[16 * 512];   // Wg1 h part
__device__ uint4 gA_h1b[16 * 512];   // Wrec1

__device__ __forceinline__ unsigned pack_h2(float a, float b) {
    __half2 h = __floats2half2_rn(a, b);
    return *reinterpret_cast<unsigned*>(&h);
}

__global__ void setup_kernel(const float* __restrict__ Win0,
                             const float* __restrict__ Wrec0,
                             const float* __restrict__ Wg0,
                             const float* __restrict__ Win1,
                             const float* __restrict__ Wrec1,
                             const float* __restrict__ Wg1) {
    int idx = blockIdx.x * 512 + threadIdx.x;   // 0 .. 55295
    const float* src; int jstr, koff; uint4* dst; int base;
    if      (idx <  2048) { dst = gA_p0a; base = 0;     src = Win0;  jstr = 96;  koff = 0;   }
    else if (idx <  4096) { dst = gA_p0b; base = 2048;  src = Wg0;   jstr = 352; koff = 0;   }
    else if (idx <  5120) { dst = gA_c0a; base = 4096;  src = Win0;  jstr = 96;  koff = 64;  }
    else if (idx <  6144) { dst = gA_c0b; base = 5120;  src = Wg0;   jstr = 352; koff = 64;  }
    else if (idx < 14336) { dst = gA_h0a; base = 6144;  src = Wg0;   jstr = 352; koff = 96;  }
    else if (idx < 22528) { dst = gA_h0b; base = 14336; src = Wrec0; jstr = 256; koff = 0;   }
    else if (idx < 30720) { dst = gA_x1a; base = 22528; src = Win1;  jstr = 256; koff = 0;   }
    else if (idx < 38912) { dst = gA_x1b; base = 30720; src = Wg1;   jstr = 512; koff = 0;   }
    else if (idx < 47104) { dst = gA_h1a; base = 38912; src = Wg1;   jstr = 512; koff = 256; }
    else                  { dst = gA_h1b; base = 47104; src = Wrec1; jstr = 256; koff = 0;   }
    int li = idx - base;
    int lane = li & 31, w = (li >> 5) & 15, kt = li >> 9;
    int r = lane >> 2, c = (lane & 3) * 2;
    int j0 = w * 16 + r, k0 = kt * 16 + c;
    const float* r0 = src + (size_t)j0 * jstr + koff;
    const float* r8 = src + (size_t)(j0 + 8) * jstr + koff;
    uint4 u;
    u.x = pack_h2(r0[k0],     r0[k0 + 1]);
    u.y = pack_h2(r8[k0],     r8[k0 + 1]);
    u.z = pack_h2(r0[k0 + 8], r0[k0 + 9]);
    u.w = pack_h2(r8[k0 + 8], r8[k0 + 9]);
    dst[li] = u;
}

// ============================================================================
// Device helpers
// ============================================================================
__device__ __forceinline__ void mma16816(float c[4], uint4 a, unsigned b0, unsigned b1) {
    asm volatile(
        "mma.sync.aligned.m16n8k16.row.col.f32.f16.f16.f32 "
        "{%0,%1,%2,%3},{%4,%5,%6,%7},{%8,%9},{%0,%1,%2,%3};"
        : "+f"(c[0]), "+f"(c[1]), "+f"(c[2]), "+f"(c[3])
        : "r"(a.x), "r"(a.y), "r"(a.z), "r"(a.w), "r"(b0), "r"(b1));
}

__device__ __forceinline__ float fast_tanh(float x) {
    float xc = fminf(fmaxf(x, -15.f), 15.f);
    float e  = __expf(2.f * xc);
    return __fdividef(e - 1.f, e + 1.f);
}
__device__ __forceinline__ float fast_sigmoid(float x) {
    return __fdividef(1.f, 1.f + __expf(-x));
}

// Dual-matrix MMA sweep over NKT 16-wide k-tiles. B packs hi (cols 0-3) and
// lo (cols 4-7) of the 4 batch rows in ONE array, so one MMA computes both
// products; the epilogue shfl_xor(2) recombines hi+lo (C cols n and n+4 live
// in lanes differing in bit 1). After combine, ALL lanes hold valid sums.
template<int NKT, int STR>
__device__ __forceinline__ void sweep2(const uint4* __restrict__ ga,
                                       const uint4* __restrict__ gb,
                                       const __half* __restrict__ B,
                                       int w, int lane,
                                       float c1[4], float c2[4]) {
    const int n  = lane >> 2;            // B column (0-3 hi, 4-7 lo)
    const int k0 = (lane & 3) * 2;
    const __half* bp = B + n * STR + k0;
    const int base = w * 32 + lane;
#pragma unroll 4
    for (int kt = 0; kt < NKT; kt++) {
        uint4 a1 = ga[kt * 512 + base];
        uint4 a2 = gb[kt * 512 + base];
        unsigned b0 = *(const unsigned*)(bp + kt * 16);
        unsigned b1 = *(const unsigned*)(bp + kt * 16 + 8);
        mma16816(c1, a1, b0, b1);
        mma16816(c2, a2, b0, b1);
    }
#pragma unroll
    for (int i = 0; i < 4; i++) {
        c1[i] += __shfl_xor_sync(0xffffffffu, c1[i], 2);
        c2[i] += __shfl_xor_sync(0xffffffffu, c2[i], 2);
    }
}

// Write a C-fragment-layout vector v into a packed hi/lo B array [8][264].
// Writing lanes (lane&3)<2 own real batch cols; they write hi at row n and
// lo at row n+4.
__device__ __forceinline__ void writeB(__half* Bp, int lane, int w, const float v[4]) {
    if ((lane & 3) < 2) {
        int n0 = (lane & 3) * 2;
        int j  = w * 16 + (lane >> 2);
#pragma unroll
        for (int e = 0; e < 4; e++) {
            int n  = n0 + (e & 1);
            int jj = j + (e >> 1) * 8;
            float vv = v[e];
            __half hv = __float2half_rn(vv);
            Bp[n * 264 + jj]       = hv;
            Bp[(n + 4) * 264 + jj] = __float2half_rn(vv - __half2float(hv));
        }
    }
}

struct __align__(16) SmemT {
    __half stA[8][264], stB[8][264];   // stage double-buffers (hi/lo packed)
    __half h0[8][264],  h1[8][264];    // layer states (h0 also = layer-1 input)
    __half xs[8][72];                  // seq features at t (K=64)
    __half cx[8][40];                  // ctx features (K=32)
    float  red[256];
    float  stats[16];
};

// One layer at one timestep: proj + 4 RK4 stages + LayerNorm + tanh.
template<int NKTP, int STRP>
__device__ __forceinline__ void layer_run(
    const uint4* __restrict__ gpa, const uint4* __restrict__ gpb,
    const __half* __restrict__ x,
    const uint4* __restrict__ gsa, const uint4* __restrict__ gsb,
    __half* __restrict__ hB,
    SmemT& sm, int tid, int w, int lane,
    const float pinI[4], const float pgI[4],
    const float it0, const float it1,
    const float lg0v, const float lg1v, const float lb0v, const float lb1v,
    float h[4]) {

    float pin[4], pg[4];
#pragma unroll
    for (int i = 0; i < 4; i++) { pin[i] = pinI[i]; pg[i] = pgI[i]; }
    sweep2<NKTP, STRP>(gpa, gpb, x, w, lane, pin, pg);

    float cg[4] = {0.f, 0.f, 0.f, 0.f}, cr[4] = {0.f, 0.f, 0.f, 0.f};
    sweep2<16, 264>(gsa, gsb, hB, w, lane, cg, cr);

    float hs[4], kacc[4];
#pragma unroll
    for (int e = 0; e < 4; e++) {                     // stage 0 epilogue
        float gg = fast_sigmoid(fast_tanh(pg[e] + cg[e]));
        float kb = pin[e] - h[e] * ((e < 2) ? it0 : it1) + gg * cr[e];
        kacc[e] = kb;
        hs[e]   = h[e] + 0.5f * kb;
    }
    writeB(&sm.stA[0][0], lane, w, hs);

    // stage 1
    __syncthreads();
#pragma unroll
    for (int i = 0; i < 4; i++) { cg[i] = 0.f; cr[i] = 0.f; }
    sweep2<16, 264>(gsa, gsb, &sm.stA[0][0], w, lane, cg, cr);
#pragma unroll
    for (int e = 0; e < 4; e++) {
        float gg = fast_sigmoid(fast_tanh(pg[e] + cg[e]));
        float kb = pin[e] - hs[e] * ((e < 2) ? it0 : it1) + gg * cr[e];
        kacc[e] += 2.f * kb;
        hs[e]    = h[e] + 0.5f * kb;
    }
    writeB(&sm.stB[0][0], lane, w, hs);

    // stage 2
    __syncthreads();
#pragma unroll
    for (int i = 0; i < 4; i++) { cg[i] = 0.f; cr[i] = 0.f; }
    sweep2<16, 264>(gsa, gsb, &sm.stB[0][0], w, lane, cg, cr);
#pragma unroll
    for (int e = 0; e < 4; e++) {
        float gg = fast_sigmoid(fast_tanh(pg[e] + cg[e]));
        float kb = pin[e] - hs[e] * ((e < 2) ? it0 : it1) + gg * cr[e];
        kacc[e] += 2.f * kb;
        hs[e]    = h[e] + kb;
    }
    writeB(&sm.stA[0][0], lane, w, hs);

    // stage 3
    __syncthreads();
#pragma unroll
    for (int i = 0; i < 4; i++) { cg[i] = 0.f; cr[i] = 0.f; }
    sweep2<16, 264>(gsa, gsb, &sm.stA[0][0], w, lane, cg, cr);
    float hn[4];
#pragma unroll
    for (int e = 0; e < 4; e++) {
        float gg = fast_sigmoid(fast_tanh(pg[e] + cg[e]));
        float kb = pin[e] - hs[e] * ((e < 2) ? it0 : it1) + gg * cr[e];
        kacc[e] += kb;
        hn[e]    = h[e] + kacc[e] * (1.f / 6.f);
    }

    // LayerNorm over j (256) per batch col
    float s0 = hn[0] + hn[2], s1 = hn[1] + hn[3];
    float q0 = hn[0] * hn[0] + hn[2] * hn[2];
    float q1 = hn[1] * hn[1] + hn[3] * hn[3];
#pragma unroll
    for (int off = 4; off <= 16; off <<= 1) {
        s0 += __shfl_xor_sync(0xffffffffu, s0, off);
        s1 += __shfl_xor_sync(0xffffffffu, s1, off);
        q0 += __shfl_xor_sync(0xffffffffu, q0, off);
        q1 += __shfl_xor_sync(0xffffffffu, q1, off);
    }
    if (lane < 4) {
        float* rp = sm.red + (w * 4 + lane) * 4;
        rp[0] = s0; rp[1] = s1; rp[2] = q0; rp[3] = q1;
    }
    __syncthreads();
    if (tid < 16) {
        float tsum = 0.f;
#pragma unroll
        for (int ww = 0; ww < 16; ww++)
            tsum += sm.red[(ww * 4 + (tid >> 2)) * 4 + (tid & 3)];
        sm.stats[tid] = tsum;
    }
    __syncthreads();
    int gq = lane & 3;
    float mu0 = sm.stats[gq * 4 + 0] * (1.f / (float)H);
    float mu1 = sm.stats[gq * 4 + 1] * (1.f / (float)H);
    float rs0 = rsqrtf(sm.stats[gq * 4 + 2] * (1.f / (float)H) - mu0 * mu0 + LN_EPS);
    float rs1 = rsqrtf(sm.stats[gq * 4 + 3] * (1.f / (float)H) - mu1 * mu1 + LN_EPS);
#pragma unroll
    for (int e = 0; e < 4; e++) {
        float mu = (e & 1) ? mu1 : mu0;
        float rs = (e & 1) ? rs1 : rs0;
        float lg = (e < 2) ? lg0v : lg1v;
        float lb = (e < 2) ? lb0v : lb1v;
        h[e] = fast_tanh((hn[e] - mu) * rs * lg + lb);   // clip is a no-op
    }
    writeB(hB, lane, w, h);
}

__global__ __launch_bounds__(512, 1)
void ltc_main(const float* __restrict__ seq,  const float* __restrict__ ctx,
              const float* __restrict__ tau0, const float* __restrict__ bg0,
              const float* __restrict__ lng0, const float* __restrict__ lnb0,
              const float* __restrict__ tau1, const float* __restrict__ bg1,
              const float* __restrict__ lng1, const float* __restrict__ lnb1,
              const float* __restrict__ cW1,  const float* __restrict__ cb1,
              const float* __restrict__ cW2,  const float* __restrict__ cb2,
              float* __restrict__ out) {
    __shared__ SmemT sm;
    int tid  = threadIdx.x;
    int lane = tid & 31, w = tid >> 5;
    int b0   = blockIdx.x * 4;

    for (int i = tid; i < (int)(sizeof(SmemT) / 4); i += 512)
        ((int*)&sm)[i] = 0;

    int r  = lane >> 2;
    int j0 = w * 16 + r, j8 = j0 + 8;

    float it0a = 1.f / (log1pf(expf(tau0[j0])) + 1.f);
    float it0b = 1.f / (log1pf(expf(tau0[j8])) + 1.f);
    float it1a = 1.f / (log1pf(expf(tau1[j0])) + 1.f);
    float it1b = 1.f / (log1pf(expf(tau1[j8])) + 1.f);
    float lg0a = lng0[j0], lg0b = lng0[j8], lb0a = lnb0[j0], lb0b = lnb0[j8];
    float lg1a = lng1[j0], lg1b = lng1[j8], lb1a = lnb1[j0], lb1b = lnb1[j8];
    float bg1a = bg1[j0],  bg1b = bg1[j8];
    float bg0a = bg0[j0],  bg0b = bg0[j8];

    __syncthreads();   // zero done

    // ---- ctx features -> cx (hi rows 0-3, lo rows 4-7) ----
    if (tid < FC) {
#pragma unroll
        for (int n = 0; n < 4; n++) {
            float v = ctx[(size_t)(b0 + n) * FC + tid];
            __half hv = __float2half_rn(v);
            sm.cx[n][tid]     = hv;
            sm.cx[n + 4][tid] = __float2half_rn(v - __half2float(hv));
        }
    }
    __syncthreads();

    // ---- ctx-folded pre-activation fragments (constant over t) ----
    float cwinF[4] = {0.f, 0.f, 0.f, 0.f}, cgF[4] = {0.f, 0.f, 0.f, 0.f};
    sweep2<2, 40>(gA_c0a, gA_c0b, &sm.cx[0][0], w, lane, cwinF, cgF);
    cgF[0] += bg0a; cgF[1] += bg0a; cgF[2] += bg0b; cgF[3] += bg0b;
    // Zero init fragments on lo-lanes so the post-sweep combine counts them once.
    if ((lane & 3) >= 2) {
#pragma unroll
        for (int i = 0; i < 4; i++) { cwinF[i] = 0.f; cgF[i] = 0.f; }
    }
    float m = ((lane & 3) < 2) ? 1.f : 0.f;
    float pin1I[4] = {0.f, 0.f, 0.f, 0.f};
    float pg1I[4]  = {bg1a * m, bg1a * m, bg1b * m, bg1b * m};

    float h0f[4] = {0.f, 0.f, 0.f, 0.f};
    float h1f[4] = {0.f, 0.f, 0.f, 0.f};

#pragma unroll 1
    for (int t = 0; t < Tsz; t++) {
        if (tid < FS) {
            size_t o = (size_t)t * FS + tid;
#pragma unroll
            for (int n = 0; n < 4; n++) {
                float v = seq[(size_t)(b0 + n) * Tsz * FS + o];
                __half hv = __float2half_rn(v);
                sm.xs[n][tid]     = hv;
                sm.xs[n + 4][tid] = __float2half_rn(v - __half2float(hv));
            }
        }
        __syncthreads();   // xs ready; h1B (prev t) ready; stage bufs free

        // ---- layer 0 ----
        layer_run<4, 72>(gA_p0a, gA_p0b, &sm.xs[0][0],
                         gA_h0a, gA_h0b, &sm.h0[0][0],
                         sm, tid, w, lane, cwinF, cgF,
                         it0a, it0b, lg0a, lg0b, lb0a, lb0b, h0f);

        __syncthreads();   // h0B ready for layer-1 proj

        // ---- layer 1 (input = h0B) ----
        layer_run<16, 264>(gA_x1a, gA_x1b, &sm.h0[0][0],
                           gA_h1a, gA_h1b, &sm.h1[0][0],
                           sm, tid, w, lane, pin1I, pg1I,
                           it1a, it1b, lg1a, lg1b, lb1a, lb1b, h1f);
        // next-t top barrier covers h1B write
    }

    // ---- head: out = relu(h1 @ cW1.T + cb1) @ cW2.T + cb2 ----
    __syncthreads();
    float* xf = (float*)&sm.stA[0][0];   // scratch (>=1024 floats across stA+stB)
    if (tid < 256) {
#pragma unroll
        for (int n = 0; n < 4; n++)
            xf[n * 256 + tid] =
                __half2float(sm.h1[n][tid]) + __half2float(sm.h1[n + 4][tid]);
    }
    __syncthreads();

    float p[4] = {0.f, 0.f, 0.f, 0.f};
    if (tid < 128) {
        float acc[4];
        float bb = cb1[tid];
#pragma unroll
        for (int b = 0; b < 4; b++) acc[b] = bb;
#pragma unroll 8
        for (int k = 0; k < H; k++) {
            float wv = cW1[tid * H + k];
            acc[0] += wv * xf[k];
            acc[1] += wv * xf[256 + k];
            acc[2] += wv * xf[512 + k];
            acc[3] += wv * xf[768 + k];
        }
        float w2 = cW2[tid];
#pragma unroll
        for (int b = 0; b < 4; b++) p[b] = fmaxf(acc[b], 0.f) * w2;
    }
#pragma unroll
    for (int off = 16; off > 0; off >>= 1) {
#pragma unroll
        for (int b = 0; b < 4; b++)
            p[b] += __shfl_xor_sync(0xffffffffu, p[b], off);
    }
    if (lane == 0) {
#pragma unroll
        for (int b = 0; b < 4; b++) sm.red[w * 4 + b] = p[b];
    }
    __syncthreads();
    if (tid < 4) {
        float o = 0.f;
#pragma unroll
        for (int ww = 0; ww < 16; ww++) o += sm.red[ww * 4 + tid];
        out[b0 + tid] = o + cb2[0];
    }
}

extern "C" void kernel_launch(void* const* d_in, const int* in_sizes, int n_in,
                              void* d_out, int out_size) {
    const float* seq   = (const float*)d_in[0];
    const float* ctx   = (const float*)d_in[1];
    const float* tau0  = (const float*)d_in[2];
    const float* Win0  = (const float*)d_in[3];
    const float* Wrec0 = (const float*)d_in[4];
    const float* Wg0   = (const float*)d_in[5];
    const float* bg0   = (const float*)d_in[6];
    const float* lng0  = (const float*)d_in[7];
    const float* lnb0  = (const float*)d_in[8];
    const float* tau1  = (const float*)d_in[9];
    const float* Win1  = (const float*)d_in[10];
    const float* Wrec1 = (const float*)d_in[11];
    const float* Wg1   = (const float*)d_in[12];
    const float* bg1   = (const float*)d_in[13];
    const float* lng1  = (const float*)d_in[14];
    const float* lnb1  = (const float*)d_in[15];
    const float* cW1   = (const float*)d_in[16];
    const float* cb1   = (const float*)d_in[17];
    const float* cW2   = (const float*)d_in[18];
    const float* cb2   = (const float*)d_in[19];
    float* out = (float*)d_out;

    setup_kernel<<<108, 512>>>(Win0, Wrec0, Wg0, Win1, Wrec1, Wg1);
    ltc_main<<<128, 512>>>(seq, ctx, tau0, bg0, lng0, lnb0,
                           tau1, bg1, lng1, lnb1,
                           cW1, cb1, cW2, cb2, out);
}